// round 16
// baseline (speedup 1.0000x reference)
#include <cuda_runtime.h>
#include <cuda_bf16.h>
#include <math.h>
#include <stdint.h>

#define Bb   16
#define Mt   16
#define Dd   512
#define Ne   16
#define Hh   682
#define HhP  688          /* padded p extent */
#define NHt  (Ne*Hh)      /* 10912 */
#define Rows (Bb*Mt)      /* 256   */
#define OUTD 512
#define YSPLIT 16
#define OSPLIT 64

typedef unsigned long long ull;
typedef __nv_bfloat16 bf16;

// ---- warp mma: D(16x8 f32) += A(16x16 bf16) * B(16x8 bf16) ----
__device__ __forceinline__ void mma_bf16(float* c, uint32_t a0, uint32_t a1, uint32_t a2, uint32_t a3,
                                         uint32_t b0, uint32_t b1) {
    asm volatile("mma.sync.aligned.m16n8k16.row.col.f32.bf16.bf16.f32 "
        "{%0,%1,%2,%3}, {%4,%5,%6,%7}, {%8,%9}, {%0,%1,%2,%3};"
        : "+f"(c[0]), "+f"(c[1]), "+f"(c[2]), "+f"(c[3])
        : "r"(a0), "r"(a1), "r"(a2), "r"(a3), "r"(b0), "r"(b1));
}

__device__ __forceinline__ void ldm_x4(uint32_t* r, uint32_t addr) {
    asm volatile("ldmatrix.sync.aligned.m8n8.x4.shared.b16 {%0,%1,%2,%3}, [%4];"
        : "=r"(r[0]), "=r"(r[1]), "=r"(r[2]), "=r"(r[3]) : "r"(addr));
}

__device__ __forceinline__ void split2(float v, bf16& h, bf16& l) {
    h = __float2bfloat16(v);
    l = __float2bfloat16(v - __bfloat162float(h));
}
__device__ __forceinline__ void st_split(bf16* gh, bf16* gl, long long idx, float v) {
    bf16 h, l; split2(v, h, l);
    gh[idx] = h; gl[idx] = l;
}

// ---- cp.async helpers ----
__device__ __forceinline__ uint32_t smem_u32(const void* p) {
    uint32_t a;
    asm("{ .reg .u64 t; cvta.to.shared.u64 t, %1; cvt.u32.u64 %0, t; }" : "=r"(a) : "l"(p));
    return a;
}
__device__ __forceinline__ void cp_async8(uint32_t dst, const void* src, int srcsz) {
    asm volatile("cp.async.ca.shared.global [%0], [%1], 8, %2;" :: "r"(dst), "l"(src), "r"(srcsz));
}
#define CP_COMMIT() asm volatile("cp.async.commit_group;" ::: "memory")
#define CP_WAIT0()  asm volatile("cp.async.wait_group 0;" ::: "memory")

// ---------------- scratch ----------------
__device__ float g_logits[Rows*NHt];
__device__ float g_XW1[Rows*NHt];
__device__ float g_Ypart[YSPLIT*Rows*OUTD];
__device__ float g_Y[Rows*OUTD];
__device__ float g_b2sum[OUTD];
__device__ float g_opart[OSPLIT*Bb*OUTD];
__device__ bf16 g_xh[Rows*Dd],  g_xl[Rows*Dd];
__device__ bf16 g_gh[Rows*NHt], g_gl[Rows*NHt];
__device__ bf16 g_chh[Rows*NHt], g_chl[Rows*NHt];
__device__ bf16 g_dwh[Bb*Ne*HhP*Mt], g_dwl[Bb*Ne*HhP*Mt];

// ---------------- prep: x split + b2sum ----------------
#define CVT_BLOCKS (Rows*Dd/4/256)      /* 128 */
__global__ void prep_k(const float* __restrict__ src, bf16* __restrict__ hi,
                       bf16* __restrict__ lo, const float* __restrict__ b2,
                       float* __restrict__ b2s)
{
    const int bx = blockIdx.x;
    if (bx < CVT_BLOCKS) {
        const int i = bx * 256 + threadIdx.x;
        const float4 v = ((const float4*)src)[i];
        bf16 h[4], l[4];
        const float vv[4] = {v.x, v.y, v.z, v.w};
        #pragma unroll
        for (int e = 0; e < 4; ++e) split2(vv[e], h[e], l[e]);
        *(ull*)(hi + i * 4) = *(const ull*)h;
        *(ull*)(lo + i * 4) = *(const ull*)l;
    } else {
        const int d = (bx - CVT_BLOCKS) * 256 + threadIdx.x;
        if (d < OUTD) {
            float s = 0.f;
            #pragma unroll
            for (int n = 0; n < Ne; ++n) s += b2[n * OUTD + d];
            b2s[d] = s;
        }
    }
}

// ---------------- combined: softmax_np + dw_split ----------------
__global__ void softdw(const float* __restrict__ L, bf16* __restrict__ chh,
                       bf16* __restrict__ chl, bf16* __restrict__ dwh,
                       bf16* __restrict__ dwl)
{
    __shared__ float s[Ne * 688];
    const int tid = threadIdx.x;

    if (blockIdx.x < Rows) {
        const int bm = blockIdx.x;
        const float* Lrow = L + bm * NHt;

        for (int i4 = tid; i4 < NHt / 4; i4 += 256) {
            const float4 v = *(const float4*)(Lrow + i4 * 4);
            const int idx = i4 * 4;
            const int n = idx / Hh;
            const int p = idx - n * Hh;
            float vv[4] = {v.x, v.y, v.z, v.w};
            int nn = n, pp = p;
            #pragma unroll
            for (int e = 0; e < 4; ++e) {
                s[nn * 688 + pp] = vv[e];
                if (++pp >= Hh) { pp = 0; ++nn; }
            }
        }
        __syncthreads();

        for (int p = tid; p < Hh; p += 256) {
            float mx = -3.4e38f;
            #pragma unroll
            for (int n = 0; n < Ne; ++n) mx = fmaxf(mx, s[n * 688 + p]);
            float sum = 0.f;
            #pragma unroll
            for (int n = 0; n < Ne; ++n) {
                const float e = expf(s[n * 688 + p] - mx);
                s[n * 688 + p] = e;
                sum += e;
            }
            const float inv = 1.f / sum;
            #pragma unroll
            for (int n = 0; n < Ne; ++n) s[n * 688 + p] *= inv;
        }
        __syncthreads();

        const int warp = tid >> 5, lane = tid & 31;
        for (int n = warp; n < Ne; n += 8) {
            float mx = -3.4e38f;
            for (int p = lane; p < Hh; p += 32) mx = fmaxf(mx, s[n * 688 + p]);
            #pragma unroll
            for (int o = 16; o; o >>= 1) mx = fmaxf(mx, __shfl_xor_sync(0xffffffffu, mx, o));
            float sum = 0.f;
            for (int p = lane; p < Hh; p += 32) {
                const float e = expf(s[n * 688 + p] - mx);
                s[n * 688 + p] = e;
                sum += e;
            }
            #pragma unroll
            for (int o = 16; o; o >>= 1) sum += __shfl_xor_sync(0xffffffffu, sum, o);
            const float inv = 1.f / sum;
            for (int p = lane; p < Hh; p += 32) {
                bf16 h, l; split2(s[n * 688 + p] * inv, h, l);
                const long long o2 = (long long)bm * NHt + n * Hh + p;
                chh[o2] = h; chl[o2] = l;
            }
        }
    } else {
        const int col = (blockIdx.x - Rows) * 256 + tid;
        const int p  = col % HhP;
        const int bn = col / HhP;
        const int b  = bn >> 4;
        const int n  = bn & (Ne - 1);

        bf16 h[Mt], l[Mt];
        if (p < Hh) {
            const long long base = ((long long)(b * Mt) * Ne + n) * Hh + p;
            float v[Mt], mx = -3.4e38f;
            #pragma unroll
            for (int m = 0; m < Mt; ++m) { v[m] = L[base + (long long)m * NHt]; mx = fmaxf(mx, v[m]); }
            float sum = 0.f;
            #pragma unroll
            for (int m = 0; m < Mt; ++m) { v[m] = expf(v[m] - mx); sum += v[m]; }
            const float inv = 1.f / sum;
            #pragma unroll
            for (int m = 0; m < Mt; ++m) split2(v[m] * inv, h[m], l[m]);
        } else {
            #pragma unroll
            for (int m = 0; m < Mt; ++m) { h[m] = __float2bfloat16(0.f); l[m] = h[m]; }
        }
        const long long o = (long long)col * Mt;
        #pragma unroll
        for (int q = 0; q < 4; ++q) {
            *(ull*)(dwh + o + q * 4) = *(const ull*)(h + q * 4);
            *(ull*)(dwl + o + q * 4) = *(const ull*)(l + q * 4);
        }
    }
}

// ---------------- mma.sync bf16-split GEMM, cp.async + ldmatrix ----------------
#define AS_STR 72             /* 144B rows, 16B aligned */
#define BS_STR 72             /* 144B rows, 16B aligned (was 74) */
#define ABUF (128*AS_STR*2)   /* 18432 */
#define BBUF (64*BS_STR*2)    /* 9216  */
#define STG_AH 0
#define STG_AL (STG_AH + ABUF)
#define STG_BH (STG_AL + ABUF)
#define STG_BL (STG_BH + BBUF)
#define STAGE  (STG_BL + BBUF)           /* 55296 */
#define MG_SMEM (2*STAGE)                /* 110592 */

template<int MODE>
__global__ __launch_bounds__(256, 2) void mma_gemm(
    const bf16* __restrict__ Ah, const bf16* __restrict__ Al,
    const float* __restrict__ Bm,
    float* __restrict__ C, int Nc, int K, int nsplit)
{
    extern __shared__ __align__(16) char sm[];
    const uint32_t smb = smem_u32(sm);

    const int t = threadIdx.x;
    const int lane = t & 31, warp = t >> 5;
    const int wm = (warp & 3) * 32;
    const int wn = (warp >> 2) * 32;
    const int m0 = blockIdx.y * 128;
    const int j0 = blockIdx.x * 64;
    const int z  = blockIdx.z;
    const int nch = (K + 63) >> 6;
    const int c0 = (int)((long long)nch * z / nsplit);
    const int c1 = (int)((long long)nch * (z + 1) / nsplit);

    float acc[2][4][4];
    #pragma unroll
    for (int i = 0; i < 2; ++i)
        #pragma unroll
        for (int j = 0; j < 4; ++j)
            #pragma unroll
            for (int e = 0; e < 4; ++e) acc[i][j][e] = 0.f;

    const int gid = lane >> 2;
    const int qid = lane & 3;

    // ldmatrix per-lane byte offsets (within a stage)
    const int lq = lane >> 3, le = lane & 7;
    uint32_t aoff[2], boff[2];
    {
        const int arow = ((lq & 1) ? 8 : 0) + le;
        const int akof = (lq & 2) ? 8 : 0;
        #pragma unroll
        for (int mi = 0; mi < 2; ++mi)
            aoff[mi] = ((wm + mi * 16 + arow) * AS_STR + akof) * 2;
        const int brow = ((lq & 2) ? 8 : 0) + le;
        const int bkof = (lq & 1) ? 8 : 0;
        #pragma unroll
        for (int pr = 0; pr < 2; ++pr)
            boff[pr] = ((wn + pr * 16 + brow) * BS_STR + bkof) * 2;
    }

    int bn[4], bh[4];
    if (MODE == 1) {
        #pragma unroll
        for (int it = 0; it < 4; ++it) {
            const int g = (t + it * 256) & 15;
            const int j = j0 + g * 4;
            int n = j / Hh;
            bn[it] = n;
            bh[it] = j - n * Hh;
        }
    }

    // ---- prologue: load chunk c0 into stage 0
    {
        const int k0 = c0 << 6;
        const uint32_t sAh = smb + STG_AH, sAl = smb + STG_AL;
        #pragma unroll
        for (int it = 0; it < 8; ++it) {
            const int s = t + it * 256;
            const int kq = s & 15, row = s >> 4;
            const int gk = k0 + kq * 4;
            const long long ga = (long long)(m0 + row) * K + gk;
            const int sz = (gk + 4 <= K) ? 8 : 0;
            const uint32_t ofs = (row * AS_STR + kq * 4) * 2;
            cp_async8(sAh + ofs, Ah + ga, sz);
            cp_async8(sAl + ofs, Al + ga, sz);
        }
        CP_COMMIT();
        bf16* sBh = (bf16*)(sm + STG_BH);
        bf16* sBl = (bf16*)(sm + STG_BL);
        #pragma unroll
        for (int it = 0; it < 4; ++it) {
            const int s = t + it * 256;
            const int g = s & 15, k = s >> 4;
            const int gj = j0 + g * 4;
            const int gk = k0 + k;
            float vv[4] = {0.f, 0.f, 0.f, 0.f};
            if (MODE == 0) {
                if (gj + 4 <= Nc && gk < K) {
                    const float4 v = *(const float4*)(Bm + (long long)gk * Nc + gj);
                    vv[0] = v.x; vv[1] = v.y; vv[2] = v.z; vv[3] = v.w;
                }
            } else {
                if (gk < K) {
                    int n = bn[it], h = bh[it];
                    #pragma unroll
                    for (int e = 0; e < 4; ++e) {
                        if (gj + e < Nc) vv[e] = Bm[((long long)n * K + gk) * Hh + h];
                        if (++h >= Hh) { h = 0; ++n; }
                    }
                }
            }
            #pragma unroll
            for (int e = 0; e < 4; ++e) {
                bf16 h, l; split2(vv[e], h, l);
                sBh[(g * 4 + e) * BS_STR + k] = h;
                sBl[(g * 4 + e) * BS_STR + k] = l;
            }
        }
        CP_WAIT0();
        __syncthreads();
    }

    for (int c = c0; c < c1; ++c) {
        const int cur = (c - c0) & 1;
        const int nxt = cur ^ 1;
        const uint32_t stg = smb + cur * STAGE;

        // ---- issue loads for chunk c+1
        if (c + 1 < c1) {
            const int k0 = (c + 1) << 6;
            const uint32_t sAh = smb + nxt * STAGE + STG_AH;
            const uint32_t sAl = smb + nxt * STAGE + STG_AL;
            #pragma unroll
            for (int it = 0; it < 8; ++it) {
                const int s = t + it * 256;
                const int kq = s & 15, row = s >> 4;
                const int gk = k0 + kq * 4;
                const long long ga = (long long)(m0 + row) * K + gk;
                const int sz = (gk + 4 <= K) ? 8 : 0;
                const uint32_t ofs = (row * AS_STR + kq * 4) * 2;
                cp_async8(sAh + ofs, Ah + ga, sz);
                cp_async8(sAl + ofs, Al + ga, sz);
            }
            CP_COMMIT();
            bf16* sBh = (bf16*)(sm + nxt * STAGE + STG_BH);
            bf16* sBl = (bf16*)(sm + nxt * STAGE + STG_BL);
            #pragma unroll
            for (int it = 0; it < 4; ++it) {
                const int s = t + it * 256;
                const int g = s & 15, k = s >> 4;
                const int gj = j0 + g * 4;
                const int gk = k0 + k;
                float vv[4] = {0.f, 0.f, 0.f, 0.f};
                if (MODE == 0) {
                    if (gj + 4 <= Nc && gk < K) {
                        const float4 v = *(const float4*)(Bm + (long long)gk * Nc + gj);
                        vv[0] = v.x; vv[1] = v.y; vv[2] = v.z; vv[3] = v.w;
                    }
                } else {
                    if (gk < K) {
                        int n = bn[it], h = bh[it];
                        #pragma unroll
                        for (int e = 0; e < 4; ++e) {
                            if (gj + e < Nc) vv[e] = Bm[((long long)n * K + gk) * Hh + h];
                            if (++h >= Hh) { h = 0; ++n; }
                        }
                    }
                }
                #pragma unroll
                for (int e = 0; e < 4; ++e) {
                    bf16 h, l; split2(vv[e], h, l);
                    sBh[(g * 4 + e) * BS_STR + k] = h;
                    sBl[(g * 4 + e) * BS_STR + k] = l;
                }
            }
        }

        // ---- compute chunk c (ldmatrix fragments)
        #pragma unroll
        for (int ks = 0; ks < 4; ++ks) {
            const uint32_t kb = ks * 32;
            uint32_t bh4[2][4], bl4[2][4];
            ldm_x4(bh4[0], stg + STG_BH + boff[0] + kb);
            ldm_x4(bh4[1], stg + STG_BH + boff[1] + kb);
            ldm_x4(bl4[0], stg + STG_BL + boff[0] + kb);
            ldm_x4(bl4[1], stg + STG_BL + boff[1] + kb);
            #pragma unroll
            for (int mi = 0; mi < 2; ++mi) {
                uint32_t ah4[4], al4[4];
                ldm_x4(ah4, stg + STG_AH + aoff[mi] + kb);
                ldm_x4(al4, stg + STG_AL + aoff[mi] + kb);
                #pragma unroll
                for (int pr = 0; pr < 2; ++pr)
                    #pragma unroll
                    for (int sub = 0; sub < 2; ++sub) {
                        const int ni = pr * 2 + sub;
                        const uint32_t b0 = bh4[pr][sub * 2], b1 = bh4[pr][sub * 2 + 1];
                        const uint32_t l0 = bl4[pr][sub * 2], l1 = bl4[pr][sub * 2 + 1];
                        mma_bf16(acc[mi][ni], ah4[0], ah4[1], ah4[2], ah4[3], b0, b1);
                        mma_bf16(acc[mi][ni], ah4[0], ah4[1], ah4[2], ah4[3], l0, l1);
                        mma_bf16(acc[mi][ni], al4[0], al4[1], al4[2], al4[3], b0, b1);
                    }
            }
        }

        if (c + 1 < c1) CP_WAIT0();
        __syncthreads();
    }

    float* Cz = C + (long long)z * Rows * Nc;
    #pragma unroll
    for (int mi = 0; mi < 2; ++mi) {
        const int r0 = m0 + wm + mi * 16 + gid;
        #pragma unroll
        for (int ni = 0; ni < 4; ++ni) {
            const int cn = j0 + wn + ni * 8 + qid * 2;
            if (cn < Nc) {
                float2 lo2 = make_float2(acc[mi][ni][0], acc[mi][ni][1]);
                float2 hi2 = make_float2(acc[mi][ni][2], acc[mi][ni][3]);
                *(float2*)(Cz + (long long)r0 * Nc + cn)       = lo2;
                *(float2*)(Cz + (long long)(r0 + 8) * Nc + cn) = hi2;
            }
        }
    }
}

// ---------------- TENSOR fused: full-h per block, pre-split Dw/Cw, prefetch ----------------
#define XH_STR 18
#define FG_SXH 0
#define FG_SXL (FG_SXH + HhP*XH_STR*2)
#define FG_SHH (FG_SXL + HhP*XH_STR*2)
#define FG_SHL (FG_SHH + HhP*XH_STR*2)
#define FG_SB   (FG_SHL + HhP*XH_STR*2)
#define FG_SMEM (FG_SB + HhP*4)          /* 101824 */
#define NTILE 86

__global__ __launch_bounds__(256, 2) void fused_G_tc(const float* __restrict__ XW1,
                                                     const bf16* __restrict__ dwh,
                                                     const bf16* __restrict__ dwl,
                                                     const bf16* __restrict__ chh,
                                                     const bf16* __restrict__ chl,
                                                     const float* __restrict__ b1,
                                                     bf16* __restrict__ gh,
                                                     bf16* __restrict__ gl)
{
    extern __shared__ __align__(16) char sm[];
    bf16*  sXh = (bf16*)(sm + FG_SXH);
    bf16*  sXl = (bf16*)(sm + FG_SXL);
    bf16*  sHh = (bf16*)(sm + FG_SHH);
    bf16*  sHl = (bf16*)(sm + FG_SHL);
    float* sb  = (float*)(sm + FG_SB);

    const int bx = blockIdx.x;
    const int n  = bx & (Ne - 1);
    const int b  = bx >> 4;
    const int t = threadIdx.x;
    const int w = t >> 5, lane = t & 31;
    const int gid = lane >> 2, qid = lane & 3;
    const long long mstep = (long long)NHt;

    for (int h = t; h < HhP; h += 256)
        sb[h] = (h < Hh) ? b1[n * Hh + h] : 0.f;

    #pragma unroll 1
    for (int mm = 0; mm < Mt; ++mm) {
        const long long rb = ((long long)(b * Mt + mm) * Ne + n) * Hh;
        for (int h = t; h < HhP; h += 256) {
            const float v = (h < Hh) ? XW1[rb + h] : 0.f;
            bf16 hi, lo; split2(v, hi, lo);
            sXh[h * XH_STR + mm] = hi;
            sXl[h * XH_STR + mm] = lo;
        }
    }
    __syncthreads();

    float acc[11][4];
    #pragma unroll
    for (int i = 0; i < 11; ++i)
        #pragma unroll
        for (int e = 0; e < 4; ++e) acc[i][e] = 0.f;

    const int NCH = 43;
    const long long dwbn = (long long)(b * Ne + n) * HhP * Mt;
    const int moff = qid * 2;
    const long long c0r = ((long long)(b * Mt + gid) * Ne + n) * Hh;
    const long long c8r = c0r + 8 * mstep;

    uint32_t dah[4], dal[4], cah[4], cal[4];
    {
        const long long r0 = dwbn + (long long)gid * Mt + moff;
        const long long r8 = r0 + 8 * Mt;
        dah[0] = *(const uint32_t*)(dwh + r0);
        dah[1] = *(const uint32_t*)(dwh + r8);
        dah[2] = *(const uint32_t*)(dwh + r0 + 8);
        dah[3] = *(const uint32_t*)(dwh + r8 + 8);
        dal[0] = *(const uint32_t*)(dwl + r0);
        dal[1] = *(const uint32_t*)(dwl + r8);
        dal[2] = *(const uint32_t*)(dwl + r0 + 8);
        dal[3] = *(const uint32_t*)(dwl + r8 + 8);
        const int k0 = qid * 2, k8 = k0 + 8;
        cah[0] = *(const uint32_t*)(chh + c0r + k0);
        cal[0] = *(const uint32_t*)(chl + c0r + k0);
        cah[1] = *(const uint32_t*)(chh + c8r + k0);
        cal[1] = *(const uint32_t*)(chl + c8r + k0);
        cah[2] = *(const uint32_t*)(chh + c0r + k8);
        cal[2] = *(const uint32_t*)(chl + c0r + k8);
        cah[3] = *(const uint32_t*)(chh + c8r + k8);
        cal[3] = *(const uint32_t*)(chl + c8r + k8);
    }

    for (int c = 0; c < NCH; ++c) {
        uint32_t ndah[4], ndal[4], ncah[4], ncal[4];
        if (c + 1 < NCH) {
            const int P0 = (c + 1) * 16;
            const long long r0 = dwbn + (long long)(P0 + gid) * Mt + moff;
            const long long r8 = r0 + 8 * Mt;
            ndah[0] = *(const uint32_t*)(dwh + r0);
            ndah[1] = *(const uint32_t*)(dwh + r8);
            ndah[2] = *(const uint32_t*)(dwh + r0 + 8);
            ndah[3] = *(const uint32_t*)(dwh + r8 + 8);
            ndal[0] = *(const uint32_t*)(dwl + r0);
            ndal[1] = *(const uint32_t*)(dwl + r8);
            ndal[2] = *(const uint32_t*)(dwl + r0 + 8);
            ndal[3] = *(const uint32_t*)(dwl + r8 + 8);
            const int k0 = P0 + qid * 2, k8 = k0 + 8;
            if (k0 + 1 < Hh) {
                ncah[0] = *(const uint32_t*)(chh + c0r + k0);
                ncal[0] = *(const uint32_t*)(chl + c0r + k0);
                ncah[1] = *(const uint32_t*)(chh + c8r + k0);
                ncal[1] = *(const uint32_t*)(chl + c8r + k0);
            } else { ncah[0] = ncal[0] = ncah[1] = ncal[1] = 0; }
            if (k8 + 1 < Hh) {
                ncah[2] = *(const uint32_t*)(chh + c0r + k8);
                ncal[2] = *(const uint32_t*)(chl + c0r + k8);
                ncah[3] = *(const uint32_t*)(chh + c8r + k8);
                ncal[3] = *(const uint32_t*)(chl + c8r + k8);
            } else { ncah[2] = ncal[2] = ncah[3] = ncal[3] = 0; }
        } else {
            #pragma unroll
            for (int i = 0; i < 4; ++i) { ndah[i] = ndal[i] = ncah[i] = ncal[i] = 0; }
        }

        #pragma unroll
        for (int ti = 0; ti < 11; ++ti) {
            const int tw = w + ti * 8;
            if (tw >= NTILE) break;
            const int hrow = tw * 8 + gid;
            const uint32_t xh0 = *(const uint32_t*)(sXh + hrow * XH_STR + qid * 2);
            const uint32_t xh1 = *(const uint32_t*)(sXh + hrow * XH_STR + qid * 2 + 8);
            const uint32_t xl0 = *(const uint32_t*)(sXl + hrow * XH_STR + qid * 2);
            const uint32_t xl1 = *(const uint32_t*)(sXl + hrow * XH_STR + qid * 2 + 8);
            float cf[4] = {0.f, 0.f, 0.f, 0.f};
            mma_bf16(cf, dah[0], dah[1], dah[2], dah[3], xh0, xh1);
            mma_bf16(cf, dah[0], dah[1], dah[2], dah[3], xl0, xl1);
            mma_bf16(cf, dal[0], dal[1], dal[2], dal[3], xh0, xh1);
            const int ha = tw * 8 + qid * 2, hb = ha + 1;
            const float ba = sb[ha], bb = sb[hb];
            const float v00 = fmaxf(cf[0] + ba, 0.f);
            const float v01 = fmaxf(cf[1] + bb, 0.f);
            const float v10 = fmaxf(cf[2] + ba, 0.f);
            const float v11 = fmaxf(cf[3] + bb, 0.f);
            bf16 hi, lo;
            split2(v00, hi, lo); sHh[ha * XH_STR + gid]     = hi; sHl[ha * XH_STR + gid]     = lo;
            split2(v01, hi, lo); sHh[hb * XH_STR + gid]     = hi; sHl[hb * XH_STR + gid]     = lo;
            split2(v10, hi, lo); sHh[ha * XH_STR + gid + 8] = hi; sHl[ha * XH_STR + gid + 8] = lo;
            split2(v11, hi, lo); sHh[hb * XH_STR + gid + 8] = hi; sHl[hb * XH_STR + gid + 8] = lo;
        }
        __syncwarp();

        #pragma unroll
        for (int ti = 0; ti < 11; ++ti) {
            const int tw = w + ti * 8;
            if (tw >= NTILE) break;
            const int hrow = tw * 8 + gid;
            const uint32_t hh0 = *(const uint32_t*)(sHh + hrow * XH_STR + qid * 2);
            const uint32_t hh1 = *(const uint32_t*)(sHh + hrow * XH_STR + qid * 2 + 8);
            const uint32_t hl0 = *(const uint32_t*)(sHl + hrow * XH_STR + qid * 2);
            const uint32_t hl1 = *(const uint32_t*)(sHl + hrow * XH_STR + qid * 2 + 8);
            mma_bf16(acc[ti], cah[0], cah[1], cah[2], cah[3], hh0, hh1);
            mma_bf16(acc[ti], cah[0], cah[1], cah[2], cah[3], hl0, hl1);
            mma_bf16(acc[ti], cal[0], cal[1], cal[2], cal[3], hh0, hh1);
        }
        __syncwarp();

        #pragma unroll
        for (int i = 0; i < 4; ++i) {
            dah[i] = ndah[i]; dal[i] = ndal[i];
            cah[i] = ncah[i]; cal[i] = ncal[i];
        }
    }

    const long long g0 = ((long long)(b * Mt + gid) * Ne + n) * Hh;
    const long long g8 = g0 + 8 * mstep;
    #pragma unroll
    for (int ti = 0; ti < 11; ++ti) {
        const int tw = w + ti * 8;
        if (tw >= NTILE) break;
        const int ha = tw * 8 + qid * 2, hb = ha + 1;
        if (ha < Hh) {
            st_split(gh, gl, g0 + ha, acc[ti][0]);
            st_split(gh, gl, g8 + ha, acc[ti][2]);
        }
        if (hb < Hh) {
            st_split(gh, gl, g0 + hb, acc[ti][1]);
            st_split(gh, gl, g8 + hb, acc[ti][3]);
        }
    }
}

// ---------------- ypart_reduce ----------------
__global__ void ypart_reduce(const float* __restrict__ part, const float* __restrict__ b2s,
                             float* __restrict__ Y)
{
    const int i4 = blockIdx.x * blockDim.x + threadIdx.x;
    const int idx = i4 * 4;
    const int col = idx & (OUTD - 1);
    float4 s = *(const float4*)(b2s + col);
    #pragma unroll
    for (int z = 0; z < YSPLIT; ++z) {
        float4 p = *(const float4*)(part + z * (Rows * OUTD) + idx);
        s.x += p.x; s.y += p.y; s.z += p.z; s.w += p.w;
    }
    *(float4*)(Y + idx) = s;
}

// ---------------- output GEMM ----------------
__global__ __launch_bounds__(128) void out_partial(const float* __restrict__ Y,
                                                   const float* __restrict__ Wout,
                                                   float* __restrict__ part)
{
    constexpr int KC = (Mt * Dd) / OSPLIT;
    __shared__ float ys[Bb][KC];
    const int tid = threadIdx.x;
    const int col = tid * 4;
    const int k0  = blockIdx.y * KC;

    for (int idx = tid; idx < Bb * KC; idx += 128) {
        const int bi = idx / KC, kk = idx - bi * KC;
        ys[bi][kk] = Y[bi * (Mt * Dd) + k0 + kk];
    }
    __syncthreads();

    float4 acc[Bb];
    #pragma unroll
    for (int bi = 0; bi < Bb; ++bi) acc[bi] = make_float4(0.f,0.f,0.f,0.f);

    for (int kk = 0; kk < KC; ++kk) {
        const float4 w = *(const float4*)(Wout + (k0 + kk) * OUTD + col);
        #pragma unroll
        for (int bi = 0; bi < Bb; ++bi) {
            const float yv = ys[bi][kk];
            acc[bi].x = fmaf(yv, w.x, acc[bi].x);
            acc[bi].y = fmaf(yv, w.y, acc[bi].y);
            acc[bi].z = fmaf(yv, w.z, acc[bi].z);
            acc[bi].w = fmaf(yv, w.w, acc[bi].w);
        }
    }
    #pragma unroll
    for (int bi = 0; bi < Bb; ++bi)
        *(float4*)(part + (blockIdx.y * Bb + bi) * OUTD + col) = acc[bi];
}

__global__ void out_reduce(const float* __restrict__ part, const float* __restrict__ bout,
                           float* __restrict__ out)
{
    const int i4 = blockIdx.x * blockDim.x + threadIdx.x;
    const int idx = i4 * 4;
    const int col = idx & (OUTD - 1);
    const int bi  = idx >> 9;
    float4 s = *(const float4*)(bout + col);
    #pragma unroll
    for (int z = 0; z < OSPLIT; ++z) {
        float4 p = *(const float4*)(part + (z * Bb + bi) * OUTD + col);
        s.x += p.x; s.y += p.y; s.z += p.z; s.w += p.w;
    }
    *(float4*)(out + idx) = s;
}

// ---------------- launch ----------------
extern "C" void kernel_launch(void* const* d_in, const int* in_sizes, int n_in,
                              void* d_out, int out_size)
{
    const float* x    = (const float*)d_in[0];
    const float* phi  = (const float*)d_in[1];
    const float* W1   = (const float*)d_in[2];
    const float* b1   = (const float*)d_in[3];
    const float* W2   = (const float*)d_in[4];
    const float* b2   = (const float*)d_in[5];
    const float* Wout = (const float*)d_in[6];
    const float* bout = (const float*)d_in[7];
    float* out = (float*)d_out;

    float *p_logits, *p_XW1, *p_Ypart, *p_Y, *p_b2sum, *p_opart;
    bf16 *p_xh, *p_xl, *p_gh, *p_gl, *p_chh, *p_chl, *p_dwh, *p_dwl;
    cudaGetSymbolAddress((void**)&p_logits, g_logits);
    cudaGetSymbolAddress((void**)&p_XW1,    g_XW1);
    cudaGetSymbolAddress((void**)&p_Ypart,  g_Ypart);
    cudaGetSymbolAddress((void**)&p_Y,      g_Y);
    cudaGetSymbolAddress((void**)&p_b2sum,  g_b2sum);
    cudaGetSymbolAddress((void**)&p_opart,  g_opart);
    cudaGetSymbolAddress((void**)&p_xh,   g_xh);
    cudaGetSymbolAddress((void**)&p_xl,   g_xl);
    cudaGetSymbolAddress((void**)&p_gh,   g_gh);
    cudaGetSymbolAddress((void**)&p_gl,   g_gl);
    cudaGetSymbolAddress((void**)&p_chh,  g_chh);
    cudaGetSymbolAddress((void**)&p_chl,  g_chl);
    cudaGetSymbolAddress((void**)&p_dwh,  g_dwh);
    cudaGetSymbolAddress((void**)&p_dwl,  g_dwl);

    cudaFuncSetAttribute(mma_gemm<0>, cudaFuncAttributeMaxDynamicSharedMemorySize, MG_SMEM);
    cudaFuncSetAttribute(mma_gemm<1>, cudaFuncAttributeMaxDynamicSharedMemorySize, MG_SMEM);
    cudaFuncSetAttribute(fused_G_tc,  cudaFuncAttributeMaxDynamicSharedMemorySize, FG_SMEM);

    const dim3 gBig((NHt + 63)/64, Rows/128, 1);             // 171 x 2

    prep_k<<<CVT_BLOCKS + 2, 256>>>(x, p_xh, p_xl, b2, p_b2sum);                 // 1
    mma_gemm<0><<<gBig, 256, MG_SMEM>>>(p_xh, p_xl, phi, p_logits, NHt, Dd, 1);  // 2
    softdw<<<Rows + (Bb*Ne*HhP)/256, 256>>>(p_logits, p_chh, p_chl, p_dwh, p_dwl); // 3
    mma_gemm<1><<<gBig, 256, MG_SMEM>>>(p_xh, p_xl, W1, p_XW1, NHt, Dd, 1);      // 4 (profiled)

    fused_G_tc<<<Bb*Ne, 256, FG_SMEM>>>(p_XW1, p_dwh, p_dwl, p_chh, p_chl, b1, p_gh, p_gl); // 5

    const dim3 gY(OUTD/64, Rows/128, YSPLIT);                // 8 x 2 x 16
    mma_gemm<0><<<gY, 256, MG_SMEM>>>(p_gh, p_gl, W2, p_Ypart, OUTD, NHt, YSPLIT); // 6
    ypart_reduce<<<(Rows*OUTD/4)/256, 256>>>(p_Ypart, p_b2sum, p_Y);             // 7

    const dim3 gO(1, OSPLIT, 1);
    out_partial<<<gO, 128>>>(p_Y, Wout, p_opart);                                 // 8
    out_reduce <<<(Bb*OUTD/4)/256, 256>>>(p_opart, bout, out);                    // 9
}

// round 17
// speedup vs baseline: 1.1043x; 1.1043x over previous
#include <cuda_runtime.h>
#include <cuda_bf16.h>
#include <math.h>
#include <stdint.h>

#define Bb   16
#define Mt   16
#define Dd   512
#define Ne   16
#define Hh   682
#define HhP  688          /* padded p extent */
#define NHt  (Ne*Hh)      /* 10912 */
#define Rows (Bb*Mt)      /* 256   */
#define OUTD 512
#define YSPLIT 16
#define OSPLIT 64

typedef unsigned long long ull;
typedef __nv_bfloat16 bf16;

// ---- warp mma: D(16x8 f32) += A(16x16 bf16) * B(16x8 bf16) ----
__device__ __forceinline__ void mma_bf16(float* c, uint32_t a0, uint32_t a1, uint32_t a2, uint32_t a3,
                                         uint32_t b0, uint32_t b1) {
    asm volatile("mma.sync.aligned.m16n8k16.row.col.f32.bf16.bf16.f32 "
        "{%0,%1,%2,%3}, {%4,%5,%6,%7}, {%8,%9}, {%0,%1,%2,%3};"
        : "+f"(c[0]), "+f"(c[1]), "+f"(c[2]), "+f"(c[3])
        : "r"(a0), "r"(a1), "r"(a2), "r"(a3), "r"(b0), "r"(b1));
}

__device__ __forceinline__ void split2(float v, bf16& h, bf16& l) {
    h = __float2bfloat16(v);
    l = __float2bfloat16(v - __bfloat162float(h));
}
__device__ __forceinline__ void st_split(bf16* gh, bf16* gl, long long idx, float v) {
    bf16 h, l; split2(v, h, l);
    gh[idx] = h; gl[idx] = l;
}

// ---- cp.async helpers ----
__device__ __forceinline__ uint32_t smem_u32(const void* p) {
    uint32_t a;
    asm("{ .reg .u64 t; cvta.to.shared.u64 t, %1; cvt.u32.u64 %0, t; }" : "=r"(a) : "l"(p));
    return a;
}
__device__ __forceinline__ void cp_async8(uint32_t dst, const void* src, int srcsz) {
    asm volatile("cp.async.ca.shared.global [%0], [%1], 8, %2;" :: "r"(dst), "l"(src), "r"(srcsz));
}
#define CP_COMMIT() asm volatile("cp.async.commit_group;" ::: "memory")
#define CP_WAIT0()  asm volatile("cp.async.wait_group 0;" ::: "memory")

// ---------------- scratch ----------------
__device__ float g_logits[Rows*NHt];
__device__ float g_XW1[Rows*NHt];
__device__ float g_Ypart[YSPLIT*Rows*OUTD];
__device__ float g_Y[Rows*OUTD];
__device__ float g_b2sum[OUTD];
__device__ float g_opart[OSPLIT*Bb*OUTD];
__device__ bf16 g_xh[Rows*Dd],  g_xl[Rows*Dd];
__device__ bf16 g_gh[Rows*NHt], g_gl[Rows*NHt];
__device__ bf16 g_chh[Rows*NHt], g_chl[Rows*NHt];
__device__ bf16 g_dwh[Bb*Ne*HhP*Mt], g_dwl[Bb*Ne*HhP*Mt];
// pre-split transposed B operands: Bt[j][k] bf16 hi/lo
__device__ bf16 g_phith[NHt*Dd],  g_phitl[NHt*Dd];    // phi^T  [NHt][Dd]
__device__ bf16 g_w1th[NHt*Dd],   g_w1tl[NHt*Dd];     // W1^T   [n*Hh+h][Dd]
__device__ bf16 g_w2th[OUTD*NHt], g_w2tl[OUTD*NHt];   // W2^T   [OUTD][NHt]

// ---------------- prep: x split + b2sum ----------------
#define CVT_BLOCKS (Rows*Dd/4/256)      /* 128 */
__global__ void prep_k(const float* __restrict__ src, bf16* __restrict__ hi,
                       bf16* __restrict__ lo, const float* __restrict__ b2,
                       float* __restrict__ b2s)
{
    const int bx = blockIdx.x;
    if (bx < CVT_BLOCKS) {
        const int i = bx * 256 + threadIdx.x;
        const float4 v = ((const float4*)src)[i];
        bf16 h[4], l[4];
        const float vv[4] = {v.x, v.y, v.z, v.w};
        #pragma unroll
        for (int e = 0; e < 4; ++e) split2(vv[e], h[e], l[e]);
        *(ull*)(hi + i * 4) = *(const ull*)h;
        *(ull*)(lo + i * 4) = *(const ull*)l;
    } else {
        const int d = (bx - CVT_BLOCKS) * 256 + threadIdx.x;
        if (d < OUTD) {
            float s = 0.f;
            #pragma unroll
            for (int n = 0; n < Ne; ++n) s += b2[n * OUTD + d];
            b2s[d] = s;
        }
    }
}

// ---------------- transpose + bf16 hi/lo split: in[R][C] f32 -> out[C][R] ----------------
// blockIdx.z gives a matrix offset of z*R*C (used for W1's expert axis).
__global__ __launch_bounds__(256) void tsplit(const float* __restrict__ in,
                                              bf16* __restrict__ oh, bf16* __restrict__ ol,
                                              int R, int C)
{
    __shared__ float tile[32][33];
    const int tx = threadIdx.x & 31, ty = threadIdx.x >> 5;
    const int c0 = blockIdx.x * 32, r0 = blockIdx.y * 32;
    const long long zofs = (long long)blockIdx.z * R * C;
    const float* inp = in + zofs;
    #pragma unroll
    for (int i = 0; i < 4; ++i) {
        const int r = r0 + ty + i * 8, c = c0 + tx;
        tile[ty + i * 8][tx] = (r < R && c < C) ? inp[(long long)r * C + c] : 0.f;
    }
    __syncthreads();
    bf16* ohp = oh + zofs;
    bf16* olp = ol + zofs;
    #pragma unroll
    for (int i = 0; i < 4; ++i) {
        const int c = c0 + ty + i * 8, r = r0 + tx;
        if (c < C && r < R) {
            bf16 h, l; split2(tile[tx][ty + i * 8], h, l);
            ohp[(long long)c * R + r] = h;
            olp[(long long)c * R + r] = l;
        }
    }
}

// ---------------- combined: softmax_np + dw_split ----------------
__global__ void softdw(const float* __restrict__ L, bf16* __restrict__ chh,
                       bf16* __restrict__ chl, bf16* __restrict__ dwh,
                       bf16* __restrict__ dwl)
{
    __shared__ float s[Ne * 688];
    const int tid = threadIdx.x;

    if (blockIdx.x < Rows) {
        const int bm = blockIdx.x;
        const float* Lrow = L + bm * NHt;

        for (int i4 = tid; i4 < NHt / 4; i4 += 256) {
            const float4 v = *(const float4*)(Lrow + i4 * 4);
            const int idx = i4 * 4;
            const int n = idx / Hh;
            const int p = idx - n * Hh;
            float vv[4] = {v.x, v.y, v.z, v.w};
            int nn = n, pp = p;
            #pragma unroll
            for (int e = 0; e < 4; ++e) {
                s[nn * 688 + pp] = vv[e];
                if (++pp >= Hh) { pp = 0; ++nn; }
            }
        }
        __syncthreads();

        for (int p = tid; p < Hh; p += 256) {
            float mx = -3.4e38f;
            #pragma unroll
            for (int n = 0; n < Ne; ++n) mx = fmaxf(mx, s[n * 688 + p]);
            float sum = 0.f;
            #pragma unroll
            for (int n = 0; n < Ne; ++n) {
                const float e = expf(s[n * 688 + p] - mx);
                s[n * 688 + p] = e;
                sum += e;
            }
            const float inv = 1.f / sum;
            #pragma unroll
            for (int n = 0; n < Ne; ++n) s[n * 688 + p] *= inv;
        }
        __syncthreads();

        const int warp = tid >> 5, lane = tid & 31;
        for (int n = warp; n < Ne; n += 8) {
            float mx = -3.4e38f;
            for (int p = lane; p < Hh; p += 32) mx = fmaxf(mx, s[n * 688 + p]);
            #pragma unroll
            for (int o = 16; o; o >>= 1) mx = fmaxf(mx, __shfl_xor_sync(0xffffffffu, mx, o));
            float sum = 0.f;
            for (int p = lane; p < Hh; p += 32) {
                const float e = expf(s[n * 688 + p] - mx);
                s[n * 688 + p] = e;
                sum += e;
            }
            #pragma unroll
            for (int o = 16; o; o >>= 1) sum += __shfl_xor_sync(0xffffffffu, sum, o);
            const float inv = 1.f / sum;
            for (int p = lane; p < Hh; p += 32) {
                bf16 h, l; split2(s[n * 688 + p] * inv, h, l);
                const long long o2 = (long long)bm * NHt + n * Hh + p;
                chh[o2] = h; chl[o2] = l;
            }
        }
    } else {
        const int col = (blockIdx.x - Rows) * 256 + tid;
        const int p  = col % HhP;
        const int bn = col / HhP;
        const int b  = bn >> 4;
        const int n  = bn & (Ne - 1);

        bf16 h[Mt], l[Mt];
        if (p < Hh) {
            const long long base = ((long long)(b * Mt) * Ne + n) * Hh + p;
            float v[Mt], mx = -3.4e38f;
            #pragma unroll
            for (int m = 0; m < Mt; ++m) { v[m] = L[base + (long long)m * NHt]; mx = fmaxf(mx, v[m]); }
            float sum = 0.f;
            #pragma unroll
            for (int m = 0; m < Mt; ++m) { v[m] = expf(v[m] - mx); sum += v[m]; }
            const float inv = 1.f / sum;
            #pragma unroll
            for (int m = 0; m < Mt; ++m) split2(v[m] * inv, h[m], l[m]);
        } else {
            #pragma unroll
            for (int m = 0; m < Mt; ++m) { h[m] = __float2bfloat16(0.f); l[m] = h[m]; }
        }
        const long long o = (long long)col * Mt;
        #pragma unroll
        for (int q = 0; q < 4; ++q) {
            *(ull*)(dwh + o + q * 4) = *(const ull*)(h + q * 4);
            *(ull*)(dwl + o + q * 4) = *(const ull*)(l + q * 4);
        }
    }
}

// ---------------- unified bf16-split GEMM: all operands pre-split, full cp.async ----------------
// C(+split-K partials) [z][256][Nc] = A[256][K] @ Bt^T, Bt[j][k] bf16 hi/lo.
#define AS_STR 72
#define BS_STR 72
#define ABUF (128*AS_STR*2)   /* 18432 */
#define BBUF (64*BS_STR*2)    /* 9216  */
#define STG_AH 0
#define STG_AL (STG_AH + ABUF)
#define STG_BH (STG_AL + ABUF)
#define STG_BL (STG_BH + BBUF)
#define STAGE  (STG_BL + BBUF)           /* 55296 */
#define MG_SMEM (2*STAGE)                /* 110592 */

__device__ __forceinline__ void gemm_load_chunk(
    uint32_t stg, const bf16* __restrict__ Ah, const bf16* __restrict__ Al,
    const bf16* __restrict__ Bh, const bf16* __restrict__ Bl,
    int t, int m0, int j0, int k0, int Nc, int K)
{
    const uint32_t sAh = stg + STG_AH, sAl = stg + STG_AL;
    #pragma unroll
    for (int it = 0; it < 8; ++it) {
        const int s = t + it * 256;
        const int kq = s & 15, row = s >> 4;
        const int gk = k0 + kq * 4;
        const long long ga = (long long)(m0 + row) * K + gk;
        const bool ok = (gk + 4 <= K);
        const uint32_t ofs = (row * AS_STR + kq * 4) * 2;
        cp_async8(sAh + ofs, ok ? (Ah + ga) : Ah, ok ? 8 : 0);
        cp_async8(sAl + ofs, ok ? (Al + ga) : Al, ok ? 8 : 0);
    }
    const uint32_t sBh = stg + STG_BH, sBl = stg + STG_BL;
    #pragma unroll
    for (int it = 0; it < 4; ++it) {
        const int s = t + it * 256;
        const int kq = s & 15, j = s >> 4;
        const int gk = k0 + kq * 4;
        const long long gb = (long long)(j0 + j) * K + gk;
        const bool ok = (j0 + j < Nc) && (gk + 4 <= K);
        const uint32_t ofs = (j * BS_STR + kq * 4) * 2;
        cp_async8(sBh + ofs, ok ? (Bh + gb) : Bh, ok ? 8 : 0);
        cp_async8(sBl + ofs, ok ? (Bl + gb) : Bl, ok ? 8 : 0);
    }
    CP_COMMIT();
}

__global__ __launch_bounds__(256, 2) void mma_gemm(
    const bf16* __restrict__ Ah, const bf16* __restrict__ Al,
    const bf16* __restrict__ Bh, const bf16* __restrict__ Bl,
    float* __restrict__ C, int Nc, int K, int nsplit)
{
    extern __shared__ __align__(16) char sm[];
    const uint32_t smb = smem_u32(sm);

    const int t = threadIdx.x;
    const int lane = t & 31, warp = t >> 5;
    const int wm = (warp & 3) * 32;
    const int wn = (warp >> 2) * 32;
    const int m0 = blockIdx.y * 128;
    const int j0 = blockIdx.x * 64;
    const int z  = blockIdx.z;
    const int nch = (K + 63) >> 6;
    const int c0 = (int)((long long)nch * z / nsplit);
    const int c1 = (int)((long long)nch * (z + 1) / nsplit);

    float acc[2][4][4];
    #pragma unroll
    for (int i = 0; i < 2; ++i)
        #pragma unroll
        for (int j = 0; j < 4; ++j)
            #pragma unroll
            for (int e = 0; e < 4; ++e) acc[i][j][e] = 0.f;

    const int gid = lane >> 2;
    const int qid = lane & 3;

    // ---- prologue: chunk c0 into stage 0
    gemm_load_chunk(smb, Ah, Al, Bh, Bl, t, m0, j0, c0 << 6, Nc, K);
    CP_WAIT0();
    __syncthreads();

    for (int c = c0; c < c1; ++c) {
        const int cur = (c - c0) & 1;
        const int nxt = cur ^ 1;
        const char* smc = sm + cur * STAGE;

        if (c + 1 < c1)
            gemm_load_chunk(smb + nxt * STAGE, Ah, Al, Bh, Bl, t, m0, j0, (c + 1) << 6, Nc, K);

        // ---- compute chunk c (scalar LDS fragments, proven R15 form)
        const bf16* sAh = (const bf16*)(smc + STG_AH);
        const bf16* sAl = (const bf16*)(smc + STG_AL);
        const bf16* sBh = (const bf16*)(smc + STG_BH);
        const bf16* sBl = (const bf16*)(smc + STG_BL);

        #pragma unroll
        for (int ks = 0; ks < 4; ++ks) {
            const int kcol = ks * 16 + qid * 2;
            uint32_t bhf[4][2], blf[4][2];
            #pragma unroll
            for (int ni = 0; ni < 4; ++ni) {
                const int n = wn + ni * 8 + gid;
                bhf[ni][0] = *(const uint32_t*)(sBh + n * BS_STR + kcol);
                bhf[ni][1] = *(const uint32_t*)(sBh + n * BS_STR + kcol + 8);
                blf[ni][0] = *(const uint32_t*)(sBl + n * BS_STR + kcol);
                blf[ni][1] = *(const uint32_t*)(sBl + n * BS_STR + kcol + 8);
            }
            #pragma unroll
            for (int mi = 0; mi < 2; ++mi) {
                const int r = wm + mi * 16 + gid;
                uint32_t ah0 = *(const uint32_t*)(sAh + r * AS_STR + kcol);
                uint32_t ah1 = *(const uint32_t*)(sAh + (r + 8) * AS_STR + kcol);
                uint32_t ah2 = *(const uint32_t*)(sAh + r * AS_STR + kcol + 8);
                uint32_t ah3 = *(const uint32_t*)(sAh + (r + 8) * AS_STR + kcol + 8);
                uint32_t al0 = *(const uint32_t*)(sAl + r * AS_STR + kcol);
                uint32_t al1 = *(const uint32_t*)(sAl + (r + 8) * AS_STR + kcol);
                uint32_t al2 = *(const uint32_t*)(sAl + r * AS_STR + kcol + 8);
                uint32_t al3 = *(const uint32_t*)(sAl + (r + 8) * AS_STR + kcol + 8);
                #pragma unroll
                for (int ni = 0; ni < 4; ++ni) {
                    mma_bf16(acc[mi][ni], ah0, ah1, ah2, ah3, bhf[ni][0], bhf[ni][1]);
                    mma_bf16(acc[mi][ni], ah0, ah1, ah2, ah3, blf[ni][0], blf[ni][1]);
                    mma_bf16(acc[mi][ni], al0, al1, al2, al3, bhf[ni][0], bhf[ni][1]);
                }
            }
        }

        if (c + 1 < c1) CP_WAIT0();
        __syncthreads();
    }

    float* Cz = C + (long long)z * Rows * Nc;
    #pragma unroll
    for (int mi = 0; mi < 2; ++mi) {
        const int r0 = m0 + wm + mi * 16 + gid;
        #pragma unroll
        for (int ni = 0; ni < 4; ++ni) {
            const int cn = j0 + wn + ni * 8 + qid * 2;
            if (cn < Nc) {
                float2 lo2 = make_float2(acc[mi][ni][0], acc[mi][ni][1]);
                float2 hi2 = make_float2(acc[mi][ni][2], acc[mi][ni][3]);
                *(float2*)(Cz + (long long)r0 * Nc + cn)       = lo2;
                *(float2*)(Cz + (long long)(r0 + 8) * Nc + cn) = hi2;
            }
        }
    }
}

// ---------------- TENSOR fused: full-h per block, pre-split Dw/Cw, prefetch ----------------
#define XH_STR 18
#define FG_SXH 0
#define FG_SXL (FG_SXH + HhP*XH_STR*2)
#define FG_SHH (FG_SXL + HhP*XH_STR*2)
#define FG_SHL (FG_SHH + HhP*XH_STR*2)
#define FG_SB   (FG_SHL + HhP*XH_STR*2)
#define FG_SMEM (FG_SB + HhP*4)          /* 101824 */
#define NTILE 86

__global__ __launch_bounds__(256, 2) void fused_G_tc(const float* __restrict__ XW1,
                                                     const bf16* __restrict__ dwh,
                                                     const bf16* __restrict__ dwl,
                                                     const bf16* __restrict__ chh,
                                                     const bf16* __restrict__ chl,
                                                     const float* __restrict__ b1,
                                                     bf16* __restrict__ gh,
                                                     bf16* __restrict__ gl)
{
    extern __shared__ __align__(16) char sm[];
    bf16*  sXh = (bf16*)(sm + FG_SXH);
    bf16*  sXl = (bf16*)(sm + FG_SXL);
    bf16*  sHh = (bf16*)(sm + FG_SHH);
    bf16*  sHl = (bf16*)(sm + FG_SHL);
    float* sb  = (float*)(sm + FG_SB);

    const int bx = blockIdx.x;
    const int n  = bx & (Ne - 1);
    const int b  = bx >> 4;
    const int t = threadIdx.x;
    const int w = t >> 5, lane = t & 31;
    const int gid = lane >> 2, qid = lane & 3;
    const long long mstep = (long long)NHt;

    for (int h = t; h < HhP; h += 256)
        sb[h] = (h < Hh) ? b1[n * Hh + h] : 0.f;

    #pragma unroll 1
    for (int mm = 0; mm < Mt; ++mm) {
        const long long rb = ((long long)(b * Mt + mm) * Ne + n) * Hh;
        for (int h = t; h < HhP; h += 256) {
            const float v = (h < Hh) ? XW1[rb + h] : 0.f;
            bf16 hi, lo; split2(v, hi, lo);
            sXh[h * XH_STR + mm] = hi;
            sXl[h * XH_STR + mm] = lo;
        }
    }
    __syncthreads();

    float acc[11][4];
    #pragma unroll
    for (int i = 0; i < 11; ++i)
        #pragma unroll
        for (int e = 0; e < 4; ++e) acc[i][e] = 0.f;

    const int NCH = 43;
    const long long dwbn = (long long)(b * Ne + n) * HhP * Mt;
    const int moff = qid * 2;
    const long long c0r = ((long long)(b * Mt + gid) * Ne + n) * Hh;
    const long long c8r = c0r + 8 * mstep;

    uint32_t dah[4], dal[4], cah[4], cal[4];
    {
        const long long r0 = dwbn + (long long)gid * Mt + moff;
        const long long r8 = r0 + 8 * Mt;
        dah[0] = *(const uint32_t*)(dwh + r0);
        dah[1] = *(const uint32_t*)(dwh + r8);
        dah[2] = *(const uint32_t*)(dwh + r0 + 8);
        dah[3] = *(const uint32_t*)(dwh + r8 + 8);
        dal[0] = *(const uint32_t*)(dwl + r0);
        dal[1] = *(const uint32_t*)(dwl + r8);
        dal[2] = *(const uint32_t*)(dwl + r0 + 8);
        dal[3] = *(const uint32_t*)(dwl + r8 + 8);
        const int k0 = qid * 2, k8 = k0 + 8;
        cah[0] = *(const uint32_t*)(chh + c0r + k0);
        cal[0] = *(const uint32_t*)(chl + c0r + k0);
        cah[1] = *(const uint32_t*)(chh + c8r + k0);
        cal[1] = *(const uint32_t*)(chl + c8r + k0);
        cah[2] = *(const uint32_t*)(chh + c0r + k8);
        cal[2] = *(const uint32_t*)(chl + c0r + k8);
        cah[3] = *(const uint32_t*)(chh + c8r + k8);
        cal[3] = *(const uint32_t*)(chl + c8r + k8);
    }

    for (int c = 0; c < NCH; ++c) {
        uint32_t ndah[4], ndal[4], ncah[4], ncal[4];
        if (c + 1 < NCH) {
            const int P0 = (c + 1) * 16;
            const long long r0 = dwbn + (long long)(P0 + gid) * Mt + moff;
            const long long r8 = r0 + 8 * Mt;
            ndah[0] = *(const uint32_t*)(dwh + r0);
            ndah[1] = *(const uint32_t*)(dwh + r8);
            ndah[2] = *(const uint32_t*)(dwh + r0 + 8);
            ndah[3] = *(const uint32_t*)(dwh + r8 + 8);
            ndal[0] = *(const uint32_t*)(dwl + r0);
            ndal[1] = *(const uint32_t*)(dwl + r8);
            ndal[2] = *(const uint32_t*)(dwl + r0 + 8);
            ndal[3] = *(const uint32_t*)(dwl + r8 + 8);
            const int k0 = P0 + qid * 2, k8 = k0 + 8;
            if (k0 + 1 < Hh) {
                ncah[0] = *(const uint32_t*)(chh + c0r + k0);
                ncal[0] = *(const uint32_t*)(chl + c0r + k0);
                ncah[1] = *(const uint32_t*)(chh + c8r + k0);
                ncal[1] = *(const uint32_t*)(chl + c8r + k0);
            } else { ncah[0] = ncal[0] = ncah[1] = ncal[1] = 0; }
            if (k8 + 1 < Hh) {
                ncah[2] = *(const uint32_t*)(chh + c0r + k8);
                ncal[2] = *(const uint32_t*)(chl + c0r + k8);
                ncah[3] = *(const uint32_t*)(chh + c8r + k8);
                ncal[3] = *(const uint32_t*)(chl + c8r + k8);
            } else { ncah[2] = ncal[2] = ncah[3] = ncal[3] = 0; }
        } else {
            #pragma unroll
            for (int i = 0; i < 4; ++i) { ndah[i] = ndal[i] = ncah[i] = ncal[i] = 0; }
        }

        #pragma unroll
        for (int ti = 0; ti < 11; ++ti) {
            const int tw = w + ti * 8;
            if (tw >= NTILE) break;
            const int hrow = tw * 8 + gid;
            const uint32_t xh0 = *(const uint32_t*)(sXh + hrow * XH_STR + qid * 2);
            const uint32_t xh1 = *(const uint32_t*)(sXh + hrow * XH_STR + qid * 2 + 8);
            const uint32_t xl0 = *(const uint32_t*)(sXl + hrow * XH_STR + qid * 2);
            const uint32_t xl1 = *(const uint32_t*)(sXl + hrow * XH_STR + qid * 2 + 8);
            float cf[4] = {0.f, 0.f, 0.f, 0.f};
            mma_bf16(cf, dah[0], dah[1], dah[2], dah[3], xh0, xh1);
            mma_bf16(cf, dah[0], dah[1], dah[2], dah[3], xl0, xl1);
            mma_bf16(cf, dal[0], dal[1], dal[2], dal[3], xh0, xh1);
            const int ha = tw * 8 + qid * 2, hb = ha + 1;
            const float ba = sb[ha], bb = sb[hb];
            const float v00 = fmaxf(cf[0] + ba, 0.f);
            const float v01 = fmaxf(cf[1] + bb, 0.f);
            const float v10 = fmaxf(cf[2] + ba, 0.f);
            const float v11 = fmaxf(cf[3] + bb, 0.f);
            bf16 hi, lo;
            split2(v00, hi, lo); sHh[ha * XH_STR + gid]     = hi; sHl[ha * XH_STR + gid]     = lo;
            split2(v01, hi, lo); sHh[hb * XH_STR + gid]     = hi; sHl[hb * XH_STR + gid]     = lo;
            split2(v10, hi, lo); sHh[ha * XH_STR + gid + 8] = hi; sHl[ha * XH_STR + gid + 8] = lo;
            split2(v11, hi, lo); sHh[hb * XH_STR + gid + 8] = hi; sHl[hb * XH_STR + gid + 8] = lo;
        }
        __syncwarp();

        #pragma unroll
        for (int ti = 0; ti < 11; ++ti) {
            const int tw = w + ti * 8;
            if (tw >= NTILE) break;
            const int hrow = tw * 8 + gid;
            const uint32_t hh0 = *(const uint32_t*)(sHh + hrow * XH_STR + qid * 2);
            const uint32_t hh1 = *(const uint32_t*)(sHh + hrow * XH_STR + qid * 2 + 8);
            const uint32_t hl0 = *(const uint32_t*)(sHl + hrow * XH_STR + qid * 2);
            const uint32_t hl1 = *(const uint32_t*)(sHl + hrow * XH_STR + qid * 2 + 8);
            mma_bf16(acc[ti], cah[0], cah[1], cah[2], cah[3], hh0, hh1);
            mma_bf16(acc[ti], cah[0], cah[1], cah[2], cah[3], hl0, hl1);
            mma_bf16(acc[ti], cal[0], cal[1], cal[2], cal[3], hh0, hh1);
        }
        __syncwarp();

        #pragma unroll
        for (int i = 0; i < 4; ++i) {
            dah[i] = ndah[i]; dal[i] = ndal[i];
            cah[i] = ncah[i]; cal[i] = ncal[i];
        }
    }

    const long long g0 = ((long long)(b * Mt + gid) * Ne + n) * Hh;
    const long long g8 = g0 + 8 * mstep;
    #pragma unroll
    for (int ti = 0; ti < 11; ++ti) {
        const int tw = w + ti * 8;
        if (tw >= NTILE) break;
        const int ha = tw * 8 + qid * 2, hb = ha + 1;
        if (ha < Hh) {
            st_split(gh, gl, g0 + ha, acc[ti][0]);
            st_split(gh, gl, g8 + ha, acc[ti][2]);
        }
        if (hb < Hh) {
            st_split(gh, gl, g0 + hb, acc[ti][1]);
            st_split(gh, gl, g8 + hb, acc[ti][3]);
        }
    }
}

// ---------------- ypart_reduce ----------------
__global__ void ypart_reduce(const float* __restrict__ part, const float* __restrict__ b2s,
                             float* __restrict__ Y)
{
    const int i4 = blockIdx.x * blockDim.x + threadIdx.x;
    const int idx = i4 * 4;
    const int col = idx & (OUTD - 1);
    float4 s = *(const float4*)(b2s + col);
    #pragma unroll
    for (int z = 0; z < YSPLIT; ++z) {
        float4 p = *(const float4*)(part + z * (Rows * OUTD) + idx);
        s.x += p.x; s.y += p.y; s.z += p.z; s.w += p.w;
    }
    *(float4*)(Y + idx) = s;
}

// ---------------- output GEMM ----------------
__global__ __launch_bounds__(128) void out_partial(const float* __restrict__ Y,
                                                   const float* __restrict__ Wout,
                                                   float* __restrict__ part)
{
    constexpr int KC = (Mt * Dd) / OSPLIT;
    __shared__ float ys[Bb][KC];
    const int tid = threadIdx.x;
    const int col = tid * 4;
    const int k0  = blockIdx.y * KC;

    for (int idx = tid; idx < Bb * KC; idx += 128) {
        const int bi = idx / KC, kk = idx - bi * KC;
        ys[bi][kk] = Y[bi * (Mt * Dd) + k0 + kk];
    }
    __syncthreads();

    float4 acc[Bb];
    #pragma unroll
    for (int bi = 0; bi < Bb; ++bi) acc[bi] = make_float4(0.f,0.f,0.f,0.f);

    for (int kk = 0; kk < KC; ++kk) {
        const float4 w = *(const float4*)(Wout + (k0 + kk) * OUTD + col);
        #pragma unroll
        for (int bi = 0; bi < Bb; ++bi) {
            const float yv = ys[bi][kk];
            acc[bi].x = fmaf(yv, w.x, acc[bi].x);
            acc[bi].y = fmaf(yv, w.y, acc[bi].y);
            acc[bi].z = fmaf(yv, w.z, acc[bi].z);
            acc[bi].w = fmaf(yv, w.w, acc[bi].w);
        }
    }
    #pragma unroll
    for (int bi = 0; bi < Bb; ++bi)
        *(float4*)(part + (blockIdx.y * Bb + bi) * OUTD + col) = acc[bi];
}

__global__ void out_reduce(const float* __restrict__ part, const float* __restrict__ bout,
                           float* __restrict__ out)
{
    const int i4 = blockIdx.x * blockDim.x + threadIdx.x;
    const int idx = i4 * 4;
    const int col = idx & (OUTD - 1);
    const int bi  = idx >> 9;
    float4 s = *(const float4*)(bout + col);
    #pragma unroll
    for (int z = 0; z < OSPLIT; ++z) {
        float4 p = *(const float4*)(part + (z * Bb + bi) * OUTD + col);
        s.x += p.x; s.y += p.y; s.z += p.z; s.w += p.w;
    }
    *(float4*)(out + idx) = s;
}

// ---------------- launch ----------------
extern "C" void kernel_launch(void* const* d_in, const int* in_sizes, int n_in,
                              void* d_out, int out_size)
{
    const float* x    = (const float*)d_in[0];
    const float* phi  = (const float*)d_in[1];
    const float* W1   = (const float*)d_in[2];
    const float* b1   = (const float*)d_in[3];
    const float* W2   = (const float*)d_in[4];
    const float* b2   = (const float*)d_in[5];
    const float* Wout = (const float*)d_in[6];
    const float* bout = (const float*)d_in[7];
    float* out = (float*)d_out;

    float *p_logits, *p_XW1, *p_Ypart, *p_Y, *p_b2sum, *p_opart;
    bf16 *p_xh, *p_xl, *p_gh, *p_gl, *p_chh, *p_chl, *p_dwh, *p_dwl;
    bf16 *p_phith, *p_phitl, *p_w1th, *p_w1tl, *p_w2th, *p_w2tl;
    cudaGetSymbolAddress((void**)&p_logits, g_logits);
    cudaGetSymbolAddress((void**)&p_XW1,    g_XW1);
    cudaGetSymbolAddress((void**)&p_Ypart,  g_Ypart);
    cudaGetSymbolAddress((void**)&p_Y,      g_Y);
    cudaGetSymbolAddress((void**)&p_b2sum,  g_b2sum);
    cudaGetSymbolAddress((void**)&p_opart,  g_opart);
    cudaGetSymbolAddress((void**)&p_xh,   g_xh);
    cudaGetSymbolAddress((void**)&p_xl,   g_xl);
    cudaGetSymbolAddress((void**)&p_gh,   g_gh);
    cudaGetSymbolAddress((void**)&p_gl,   g_gl);
    cudaGetSymbolAddress((void**)&p_chh,  g_chh);
    cudaGetSymbolAddress((void**)&p_chl,  g_chl);
    cudaGetSymbolAddress((void**)&p_dwh,  g_dwh);
    cudaGetSymbolAddress((void**)&p_dwl,  g_dwl);
    cudaGetSymbolAddress((void**)&p_phith, g_phith);
    cudaGetSymbolAddress((void**)&p_phitl, g_phitl);
    cudaGetSymbolAddress((void**)&p_w1th,  g_w1th);
    cudaGetSymbolAddress((void**)&p_w1tl,  g_w1tl);
    cudaGetSymbolAddress((void**)&p_w2th,  g_w2th);
    cudaGetSymbolAddress((void**)&p_w2tl,  g_w2tl);

    cudaFuncSetAttribute(mma_gemm,   cudaFuncAttributeMaxDynamicSharedMemorySize, MG_SMEM);
    cudaFuncSetAttribute(fused_G_tc, cudaFuncAttributeMaxDynamicSharedMemorySize, FG_SMEM);

    const dim3 gBig((NHt + 63)/64, Rows/128, 1);             // 171 x 2

    // 1: phi^T split  [Dd][NHt] -> [NHt][Dd]
    tsplit<<<dim3((NHt+31)/32, Dd/32, 1), 256>>>(phi, p_phith, p_phitl, Dd, NHt);
    // 2: W1^T split   per expert [Dd][Hh] -> [Hh][Dd]
    tsplit<<<dim3((Hh+31)/32, Dd/32, Ne), 256>>>(W1, p_w1th, p_w1tl, Dd, Hh);
    // 3: x split + b2sum
    prep_k<<<CVT_BLOCKS + 2, 256>>>(x, p_xh, p_xl, b2, p_b2sum);
    // 4 (profiled): logits GEMM
    mma_gemm<<<gBig, 256, MG_SMEM>>>(p_xh, p_xl, p_phith, p_phitl, p_logits, NHt, Dd, 1);
    // 5: XW1 GEMM
    mma_gemm<<<gBig, 256, MG_SMEM>>>(p_xh, p_xl, p_w1th, p_w1tl, p_XW1, NHt, Dd, 1);
    // 6: softmaxes
    softdw<<<Rows + (Bb*Ne*HhP)/256, 256>>>(p_logits, p_chh, p_chl, p_dwh, p_dwl);
    // 7: W2^T split   [NHt][OUTD] -> [OUTD][NHt]
    tsplit<<<dim3(OUTD/32, (NHt+31)/32, 1), 256>>>(W2, p_w2th, p_w2tl, NHt, OUTD);
    // 8: fused mix->relu->combine
    fused_G_tc<<<Bb*Ne, 256, FG_SMEM>>>(p_XW1, p_dwh, p_dwl, p_chh, p_chl, b1, p_gh, p_gl);
    // 9: Y GEMM (split-K)
    const dim3 gY(OUTD/64, Rows/128, YSPLIT);
    mma_gemm<<<gY, 256, MG_SMEM>>>(p_gh, p_gl, p_w2th, p_w2tl, p_Ypart, OUTD, NHt, YSPLIT);
    // 10-12: reductions + output
    ypart_reduce<<<(Rows*OUTD/4)/256, 256>>>(p_Ypart, p_b2sum, p_Y);
    const dim3 gO(1, OSPLIT, 1);
    out_partial<<<gO, 128>>>(p_Y, Wout, p_opart);
    out_reduce <<<(Bb*OUTD/4)/256, 256>>>(p_opart, bout, out);
}